// round 3
// baseline (speedup 1.0000x reference)
#include <cuda_runtime.h>
#include <cstdint>
#include <cstddef>

#define N_ROWS   262144
#define DDIM     64
#define QSTAGES  8
#define KCODES   1024
#define TM       128
#define TN       128
#define NTHREADS 256
#define TPAD     132
#define CPAD     132

// shared memory layout (float units)
#define OFF_XT   0
#define OFF_QT   (OFF_XT + DDIM * TPAD)
#define OFF_RT   (OFF_QT + DDIM * TPAD)
#define OFF_CB   (OFF_RT + DDIM * TPAD)          // double-buffered codebook chunk
#define OFF_HN   (OFF_CB + 2 * DDIM * CPAD)
#define OFF_IDX  (OFF_HN + KCODES)               // TM ints
#define SMEM_FLOATS (OFF_IDX + TM)
#define SMEM_BYTES  (SMEM_FLOATS * 4)

// hn[q][k] = XLA-emulated fp32 sum(cb*cb) (warp-tree reduction, see hn_kernel)
__device__ float g_hn[QSTAGES * KCODES];

// ---------------- packed f32x2 helpers ----------------
__device__ __forceinline__ void ffma2(unsigned long long& acc,
                                      unsigned long long a,
                                      unsigned long long b) {
    asm("fma.rn.f32x2 %0, %1, %2, %0;" : "+l"(acc) : "l"(a), "l"(b));
}
__device__ __forceinline__ unsigned long long dup2(float v) {
    unsigned long long r;
    asm("mov.b64 %0, {%1, %1};" : "=l"(r) : "f"(v));
    return r;
}
__device__ __forceinline__ float2 unpack2(unsigned long long p) {
    float2 r;
    asm("mov.b64 {%0, %1}, %2;" : "=f"(r.x), "=f"(r.y) : "l"(p));
    return r;
}

// ---------------- codebook norms: emulate XLA row-reduction ----------------
// One warp per code. Lane l accumulates elements l and l+32 (fma-contracted),
// then shfl.down tree (16,8,4,2,1). Lane 0 holds the reference-identical sum.
__global__ void hn_kernel(const float* __restrict__ cb) {
    int warp = (blockIdx.x * blockDim.x + threadIdx.x) >> 5;
    int lane = threadIdx.x & 31;
    if (warp < QSTAGES * KCODES) {
        const float* row = cb + (size_t)warp * DDIM;
        float c0 = row[lane];
        float c1 = row[lane + 32];
        float acc = __fmaf_rn(c0, c0, 0.0f);
        acc = __fmaf_rn(c1, c1, acc);
#pragma unroll
        for (int off = 16; off > 0; off >>= 1) {
            float sh = __shfl_down_sync(0xffffffffu, acc, off);
            acc = acc + sh;
        }
        if (lane == 0) g_hn[warp] = acc;
    }
}

// ---------------- codebook chunk staging ----------------
__device__ __forceinline__ void load_chunk(const float* __restrict__ cbq, int c,
                                           int tid, float4* st) {
    int klocal = tid >> 1;
    int d0 = (tid & 1) << 5;
    const float4* p = reinterpret_cast<const float4*>(
        cbq + ((size_t)(c * TN + klocal)) * DDIM + d0);
#pragma unroll
    for (int j = 0; j < 8; j++) st[j] = p[j];
}
__device__ __forceinline__ void sts_chunk(float* __restrict__ buf, int tid,
                                          const float4* st) {
    int klocal = tid >> 1;
    int d0 = (tid & 1) << 5;
#pragma unroll
    for (int j = 0; j < 8; j++) {
        int dd = d0 + (j << 2);
        buf[(dd + 0) * CPAD + klocal] = st[j].x;
        buf[(dd + 1) * CPAD + klocal] = st[j].y;
        buf[(dd + 2) * CPAD + klocal] = st[j].z;
        buf[(dd + 3) * CPAD + klocal] = st[j].w;
    }
}

// ---------------- main fused RVQ kernel ----------------
__global__ void __launch_bounds__(NTHREADS, 1)
rvq_kernel(const float* __restrict__ x, const float* __restrict__ cb,
           float* __restrict__ qz, float* __restrict__ enc_f,
           int* __restrict__ enc_i) {
    extern __shared__ float smem[];
    float* s_xT  = smem + OFF_XT;
    float* s_qT  = smem + OFF_QT;
    float* s_rT  = smem + OFF_RT;
    float* s_cbT = smem + OFF_CB;
    float* s_hn  = smem + OFF_HN;
    int*   s_idx = reinterpret_cast<int*>(smem + OFF_IDX);

    const int tid = threadIdx.x;
    const int tx = tid & 15;
    const int ty = tid >> 4;
    const int row_base = blockIdx.x * TM;

    // ---- init: xT = x (transposed), qT = 0, rT = x ----
    {
        int n = tid >> 1;
        int d0 = (tid & 1) << 5;
        const float4* xp = reinterpret_cast<const float4*>(
            x + (size_t)(row_base + n) * DDIM + d0);
#pragma unroll
        for (int j = 0; j < 8; j++) {
            float4 v = xp[j];
            int dd = d0 + (j << 2);
            s_xT[(dd + 0) * TPAD + n] = v.x;
            s_xT[(dd + 1) * TPAD + n] = v.y;
            s_xT[(dd + 2) * TPAD + n] = v.z;
            s_xT[(dd + 3) * TPAD + n] = v.w;
            s_qT[(dd + 0) * TPAD + n] = 0.f;
            s_qT[(dd + 1) * TPAD + n] = 0.f;
            s_qT[(dd + 2) * TPAD + n] = 0.f;
            s_qT[(dd + 3) * TPAD + n] = 0.f;
            s_rT[(dd + 0) * TPAD + n] = v.x;
            s_rT[(dd + 1) * TPAD + n] = v.y;
            s_rT[(dd + 2) * TPAD + n] = v.z;
            s_rT[(dd + 3) * TPAD + n] = v.w;
        }
    }

    for (int q = 0; q < QSTAGES; q++) {
        const float* cbq = cb + (size_t)q * (KCODES * DDIM);

        for (int i = tid; i < KCODES; i += NTHREADS)
            s_hn[i] = g_hn[q * KCODES + i];
        __syncthreads();

        // prologue: chunk 0 -> buffer 0
        float4 st[8];
        load_chunk(cbq, 0, tid, st);
        sts_chunk(s_cbT + 0, tid, st);
        __syncthreads();

        // per-lane running argmin of d = fma(-2, s, hn)  (first-min tie-break:
        // within a lane indices are visited ascending, so strict < keeps first)
        float bestd[8];
        int besti[8];
#pragma unroll
        for (int i = 0; i < 8; i++) { bestd[i] = 3.0e38f; besti[i] = 0x7fffffff; }

        for (int c = 0; c < KCODES / TN; c++) {
            if (c < KCODES / TN - 1) load_chunk(cbq, c + 1, tid, st);

            const float* bufb = s_cbT + (c & 1) * (DDIM * CPAD);

            unsigned long long acc[8][4];
#pragma unroll
            for (int i = 0; i < 8; i++)
#pragma unroll
                for (int j = 0; j < 4; j++) acc[i][j] = 0ULL;

            // s = sum_d r[d]*c[d], fma, d ascending, single accumulator per
            // output (per packed half) — bit-identical to SGEMM's k-loop.
#pragma unroll 4
            for (int d = 0; d < DDIM; d++) {
                const float* rrow = s_rT + d * TPAD + (ty << 3);
                float4 a0 = *reinterpret_cast<const float4*>(rrow);
                float4 a1 = *reinterpret_cast<const float4*>(rrow + 4);
                const ulonglong2* bp = reinterpret_cast<const ulonglong2*>(
                    bufb + d * CPAD + (tx << 3));
                ulonglong2 b0 = bp[0];
                ulonglong2 b1 = bp[1];
                float av[8] = {a0.x, a0.y, a0.z, a0.w, a1.x, a1.y, a1.z, a1.w};
#pragma unroll
                for (int i = 0; i < 8; i++) {
                    unsigned long long ad = dup2(av[i]);
                    ffma2(acc[i][0], ad, b0.x);
                    ffma2(acc[i][1], ad, b0.y);
                    ffma2(acc[i][2], ad, b1.x);
                    ffma2(acc[i][3], ad, b1.y);
                }
            }

            // epilogue: d = fma(-2, s, hn)  (== RN(-2s + hn), identical to
            // reference's -2*s + hn since -2*s is exact) ; running strict min
            {
                int colbase = c * TN + (tx << 3);
                float hnv[8];
                *reinterpret_cast<float4*>(hnv) =
                    *reinterpret_cast<const float4*>(s_hn + colbase);
                *reinterpret_cast<float4*>(hnv + 4) =
                    *reinterpret_cast<const float4*>(s_hn + colbase + 4);
#pragma unroll
                for (int i = 0; i < 8; i++) {
#pragma unroll
                    for (int j = 0; j < 4; j++) {
                        float2 v = unpack2(acc[i][j]);
                        int c0 = colbase + 2 * j;
                        float d0v = __fmaf_rn(-2.0f, v.x, hnv[2 * j]);
                        float d1v = __fmaf_rn(-2.0f, v.y, hnv[2 * j + 1]);
                        if (d0v < bestd[i]) { bestd[i] = d0v; besti[i] = c0; }
                        if (d1v < bestd[i]) { bestd[i] = d1v; besti[i] = c0 + 1; }
                    }
                }
            }

            if (c < KCODES / TN - 1) {
                sts_chunk(s_cbT + ((c + 1) & 1) * (DDIM * CPAD), tid, st);
                __syncthreads();
            }
        }

        // cross-lane argmin merge over 16 tx lanes ((d, idx) lexicographic:
        // smaller d wins; equal d -> lower index == first occurrence)
#pragma unroll
        for (int i = 0; i < 8; i++) {
#pragma unroll
            for (int off = 8; off > 0; off >>= 1) {
                float ov = __shfl_xor_sync(0xffffffffu, bestd[i], off);
                int oi = __shfl_xor_sync(0xffffffffu, besti[i], off);
                if (ov < bestd[i] || (ov == bestd[i] && oi < besti[i])) {
                    bestd[i] = ov;
                    besti[i] = oi;
                }
            }
        }
        if (tx == 0) {
#pragma unroll
            for (int i = 0; i < 8; i++) {
                int row = (ty << 3) + i;
                int id = besti[i];
                s_idx[row] = id;
                size_t e = (size_t)(row_base + row) * QSTAGES + q;
                if (enc_f) enc_f[e] = (float)id;
                if (enc_i) enc_i[e] = id;
            }
        }
        __syncthreads();

        // ---- update: q += cb[idx] (fp32, ref order); r = x - q ----
        {
            int n = tid >> 1;
            int d0 = (tid & 1) << 5;
            int id = s_idx[n];
            const float4* cp = reinterpret_cast<const float4*>(
                cbq + (size_t)id * DDIM + d0);
#pragma unroll
            for (int j = 0; j < 8; j++) {
                float4 v = cp[j];
                int dd = d0 + (j << 2);
                float qv0 = s_qT[(dd + 0) * TPAD + n] + v.x;
                float qv1 = s_qT[(dd + 1) * TPAD + n] + v.y;
                float qv2 = s_qT[(dd + 2) * TPAD + n] + v.z;
                float qv3 = s_qT[(dd + 3) * TPAD + n] + v.w;
                s_qT[(dd + 0) * TPAD + n] = qv0;
                s_qT[(dd + 1) * TPAD + n] = qv1;
                s_qT[(dd + 2) * TPAD + n] = qv2;
                s_qT[(dd + 3) * TPAD + n] = qv3;
                s_rT[(dd + 0) * TPAD + n] = s_xT[(dd + 0) * TPAD + n] - qv0;
                s_rT[(dd + 1) * TPAD + n] = s_xT[(dd + 1) * TPAD + n] - qv1;
                s_rT[(dd + 2) * TPAD + n] = s_xT[(dd + 2) * TPAD + n] - qv2;
                s_rT[(dd + 3) * TPAD + n] = s_xT[(dd + 3) * TPAD + n] - qv3;
            }
        }
        __syncthreads();
    }

    // ---- output quantized = qT (bit-exact accumulation) ----
    if (qz) {
        int n = tid >> 1;
        int d0 = (tid & 1) << 5;
        size_t base = (size_t)(row_base + n) * DDIM + d0;
#pragma unroll
        for (int j = 0; j < 8; j++) {
            int dd = d0 + (j << 2);
            float4 o;
            o.x = s_qT[(dd + 0) * TPAD + n];
            o.y = s_qT[(dd + 1) * TPAD + n];
            o.z = s_qT[(dd + 2) * TPAD + n];
            o.w = s_qT[(dd + 3) * TPAD + n];
            *reinterpret_cast<float4*>(qz + base + (j << 2)) = o;
        }
    }
}

// ---------------- launch ----------------
extern "C" void kernel_launch(void* const* d_in, const int* in_sizes, int n_in,
                              void* d_out, int out_size) {
    const float* x = (const float*)d_in[0];
    const float* cb = (const float*)d_in[1];
    if (n_in >= 2 && in_sizes[0] == QSTAGES * KCODES * DDIM &&
        in_sizes[1] == N_ROWS * DDIM) {
        x = (const float*)d_in[1];
        cb = (const float*)d_in[0];
    }

    cudaFuncSetAttribute(rvq_kernel, cudaFuncAttributeMaxDynamicSharedMemorySize,
                         SMEM_BYTES);

    // one warp per code
    hn_kernel<<<(QSTAGES * KCODES * 32 + 255) / 256, 256>>>(cb);

    const long long enc_n = (long long)N_ROWS * QSTAGES;
    const long long qz_n = (long long)N_ROWS * DDIM;

    float* qz = nullptr;
    float* enc_f = nullptr;
    int* enc_i = nullptr;
    if ((long long)out_size == enc_n + qz_n) {
        enc_f = (float*)d_out;
        qz = (float*)d_out + enc_n;
    } else if ((long long)out_size == qz_n) {
        qz = (float*)d_out;
    } else if ((long long)out_size == enc_n) {
        enc_i = (int*)d_out;
    } else {
        enc_f = (float*)d_out;
        if ((long long)out_size >= enc_n + qz_n) qz = (float*)d_out + enc_n;
    }

    rvq_kernel<<<N_ROWS / TM, NTHREADS, SMEM_BYTES>>>(x, cb, qz, enc_f, enc_i);
}